// round 2
// baseline (speedup 1.0000x reference)
#include <cuda_runtime.h>
#include <cstdint>

// Problem dims (fixed by the reference)
#define BATCH 8
#define SEQ 2048
#define DIM 1024                    // INPUT_DIM == STATE_DIM == OUTPUT_DIM == 1024
#define M_TOTAL (BATCH * SEQ)       // 16384 rows

// 64 MB scratch for u (then h, scan runs in-place). __device__ global: no alloc.
__device__ float g_state_buf[(size_t)BATCH * SEQ * DIM];

// ---------------------------------------------------------------------------
// Classic 128x128x8 fp32 SGEMM, NT form:
//   C[m,n] = sum_k A[m,k] * B[n,k]  (+ bias[n] if add_bias)
// A is MxK row-major, B is NxK row-major. 256 threads, 8x8 per-thread tile
// split into 4x 4x4 quadrants (conflict-free float4 LDS).
// ---------------------------------------------------------------------------
__global__ void __launch_bounds__(256, 2)
sgemm_nt(const float* __restrict__ A, const float* __restrict__ B,
         const float* __restrict__ bias, float* __restrict__ C,
         int M, int N, int K, int add_bias)
{
    __shared__ float As[8][128];
    __shared__ float Bs[8][128];

    const int tid = threadIdx.x;
    const int bm  = blockIdx.y * 128;
    const int bn  = blockIdx.x * 128;

    // global->smem load mapping: 2 threads per row, float4 each (8 k-floats/row)
    const int lrow = tid >> 1;          // 0..127
    const int lk   = (tid & 1) * 4;     // 0 or 4

    // compute mapping: 16x16 threads, each owns rows {ty*4..+3, 64+ty*4..+3}
    // and cols {tx*4..+3, 64+tx*4..+3}
    const int tx = tid & 15;
    const int ty = tid >> 4;

    const float* Ag = A + (size_t)(bm + lrow) * K + lk;
    const float* Bg = B + (size_t)(bn + lrow) * K + lk;

    float acc[8][8];
#pragma unroll
    for (int i = 0; i < 8; i++)
#pragma unroll
        for (int j = 0; j < 8; j++) acc[i][j] = 0.0f;

    for (int k0 = 0; k0 < K; k0 += 8) {
        float4 av = *reinterpret_cast<const float4*>(Ag);
        float4 bv = *reinterpret_cast<const float4*>(Bg);
        Ag += 8;
        Bg += 8;

        As[lk + 0][lrow] = av.x;
        As[lk + 1][lrow] = av.y;
        As[lk + 2][lrow] = av.z;
        As[lk + 3][lrow] = av.w;
        Bs[lk + 0][lrow] = bv.x;
        Bs[lk + 1][lrow] = bv.y;
        Bs[lk + 2][lrow] = bv.z;
        Bs[lk + 3][lrow] = bv.w;
        __syncthreads();

#pragma unroll
        for (int k = 0; k < 8; k++) {
            float4 a0 = *reinterpret_cast<const float4*>(&As[k][ty * 4]);
            float4 a1 = *reinterpret_cast<const float4*>(&As[k][64 + ty * 4]);
            float4 b0 = *reinterpret_cast<const float4*>(&Bs[k][tx * 4]);
            float4 b1 = *reinterpret_cast<const float4*>(&Bs[k][64 + tx * 4]);
            float af[8] = {a0.x, a0.y, a0.z, a0.w, a1.x, a1.y, a1.z, a1.w};
            float bf[8] = {b0.x, b0.y, b0.z, b0.w, b1.x, b1.y, b1.z, b1.w};
#pragma unroll
            for (int i = 0; i < 8; i++)
#pragma unroll
                for (int j = 0; j < 8; j++)
                    acc[i][j] = fmaf(af[i], bf[j], acc[i][j]);
        }
        __syncthreads();
    }

    // epilogue: 4 quadrants of 4x4, float4 stores
#pragma unroll
    for (int qi = 0; qi < 2; qi++) {
#pragma unroll
        for (int i = 0; i < 4; i++) {
            const int row = bm + qi * 64 + ty * 4 + i;
#pragma unroll
            for (int qj = 0; qj < 2; qj++) {
                const int col = bn + qj * 64 + tx * 4;
                float4 v = make_float4(acc[qi * 4 + i][qj * 4 + 0],
                                       acc[qi * 4 + i][qj * 4 + 1],
                                       acc[qi * 4 + i][qj * 4 + 2],
                                       acc[qi * 4 + i][qj * 4 + 3]);
                if (add_bias) {
                    v.x += bias[col + 0];
                    v.y += bias[col + 1];
                    v.z += bias[col + 2];
                    v.w += bias[col + 3];
                }
                *reinterpret_cast<float4*>(&C[(size_t)row * N + col]) = v;
            }
        }
    }
}

// ---------------------------------------------------------------------------
// Diagonal linear recurrence, in place on g_state_buf:
//   h_t = A[n] * h_{t-1} + u_t,   h_0init = 0
// One thread per (batch, state) pair: 8192 threads, coalesced over n.
// ---------------------------------------------------------------------------
__global__ void __launch_bounds__(256)
ssm_scan_kernel(const float* __restrict__ Avec)
{
    const int idx = blockIdx.x * blockDim.x + threadIdx.x;  // 0..8191
    const int b = idx >> 10;
    const int n = idx & 1023;
    const float a = Avec[n];

    float* p = g_state_buf + (size_t)b * SEQ * DIM + n;
    float h = 0.0f;
#pragma unroll 8
    for (int t = 0; t < SEQ; t++) {
        h = fmaf(a, h, p[(size_t)t * DIM]);
        p[(size_t)t * DIM] = h;
    }
}

// ---------------------------------------------------------------------------
// kernel_launch: u = x * B^T ; scan ; y = h * W^T + bias
// inputs (metadata order): x, A, B, W, b
// ---------------------------------------------------------------------------
extern "C" void kernel_launch(void* const* d_in, const int* in_sizes, int n_in,
                              void* d_out, int out_size)
{
    const float* x    = (const float*)d_in[0];  // [8, 2048, 1024]
    const float* Avec = (const float*)d_in[1];  // [1024]
    const float* Bmat = (const float*)d_in[2];  // [1024, 1024] (state, input)
    const float* Wmat = (const float*)d_in[3];  // [1024, 1024] (output, state)
    const float* bias = (const float*)d_in[4];  // [1024]
    float* out = (float*)d_out;                 // [8, 2048, 1024]

    float* buf = nullptr;
    cudaGetSymbolAddress((void**)&buf, g_state_buf);

    dim3 grid(DIM / 128, M_TOTAL / 128);  // (8, 128)

    // u = x @ B^T   -> g_state_buf
    sgemm_nt<<<grid, 256>>>(x, Bmat, nullptr, buf, M_TOTAL, DIM, DIM, 0);

    // h_t = A*h_{t-1} + u_t, in place
    ssm_scan_kernel<<<(BATCH * DIM) / 256, 256>>>(Avec);

    // y = h @ W^T + bias
    sgemm_nt<<<grid, 256>>>(buf, Wmat, bias, out, M_TOTAL, DIM, DIM, 1);
}

// round 5
// speedup vs baseline: 3.2730x; 3.2730x over previous
#include <cuda_runtime.h>
#include <cstdint>

#define BATCH 8
#define SEQ 2048
#define DIM 1024
#define M_TOTAL (BATCH * SEQ)

// GEMM tiling
#define BM 128
#define BN 128
#define BK 32
#define KTILES (DIM / BK)        // 32
#define LDT 36                   // padded smem row length (floats): (4r+c)%32 conflict-free
#define STAGEF (2 * BM * LDT)    // floats per stage (A tile + B tile)
#define NSTAGES 3
#define SMEM_BYTES (NSTAGES * STAGEF * 4)   // 110592

// scan chunking
#define CHUNKS 16
#define CLEN (SEQ / CHUNKS)      // 128

// -------------------- scratch (static device globals, no alloc) ------------
__device__ float g_u[(size_t)M_TOTAL * DIM];   // u, then h in place
__device__ float g_carry[BATCH * CHUNKS * DIM];
__device__ float g_prefix[BATCH * CHUNKS * DIM];

// -------------------- helpers ----------------------------------------------
__device__ __forceinline__ uint32_t smem_u32(const void* p) {
    uint32_t a;
    asm("{ .reg .u64 t; cvta.to.shared.u64 t, %1; cvt.u32.u64 %0, t; }" : "=r"(a) : "l"(p));
    return a;
}
__device__ __forceinline__ uint32_t rtf32_u(float x) {
    uint32_t r;
    asm("cvt.rna.tf32.f32 %0, %1;" : "=r"(r) : "f"(x));
    return r;
}
#define CP_ASYNC16(dst, src) \
    asm volatile("cp.async.cg.shared.global [%0], [%1], 16;" :: "r"(dst), "l"(src))

__device__ __forceinline__ void mma_tf32(float* d, const uint32_t* a, const uint32_t* b) {
    asm volatile(
        "mma.sync.aligned.m16n8k8.row.col.f32.tf32.tf32.f32 "
        "{%0,%1,%2,%3}, {%4,%5,%6,%7}, {%8,%9}, {%0,%1,%2,%3};"
        : "+f"(d[0]), "+f"(d[1]), "+f"(d[2]), "+f"(d[3])
        : "r"(a[0]), "r"(a[1]), "r"(a[2]), "r"(a[3]), "r"(b[0]), "r"(b[1]));
}

// -------------------- tf32 mma.sync GEMM -----------------------------------
// C[m,n] = sum_k A[m,k]*B[n,k] (+bias[n]). A: MxK row-major, B: NxK row-major.
// K = N = 1024 fixed. Operands tf32-rounded in-register (cvt.rna).
__global__ void __launch_bounds__(256, 2)
gemm_tf32mma(const float* __restrict__ A, const float* __restrict__ Bm,
             const float* __restrict__ bias, float* __restrict__ C,
             int add_bias)
{
    extern __shared__ float sm[];
    const int tid = threadIdx.x;
    const int wid = tid >> 5, lid = tid & 31;
    const int g = lid >> 2, tg = lid & 3;       // mma quad coords
    const int warp_m = wid >> 2;                // 0..1 (64 rows each)
    const int warp_n = wid & 3;                 // 0..3 (32 cols each)
    const int bm = blockIdx.y * BM, bn = blockIdx.x * BN;

    const uint32_t sbase = smem_u32(sm);
    // global load mapping: idx -> (row, 16B chunk)
    const int lr = tid >> 1;                    // reused per-iteration below

    float acc[4][4][4];
#pragma unroll
    for (int mi = 0; mi < 4; mi++)
#pragma unroll
        for (int ni = 0; ni < 4; ni++)
#pragma unroll
            for (int q = 0; q < 4; q++) acc[mi][ni][q] = 0.0f;
    (void)lr;

    // ---- stage loader ----
    auto load_stage = [&](int buf, int kt) {
        const uint32_t sa = sbase + (uint32_t)(buf * STAGEF) * 4u;
        const uint32_t sb2 = sa + (uint32_t)(BM * LDT) * 4u;
        const float* Ag = A + (size_t)bm * DIM + kt * BK;
        const float* Bg = Bm + (size_t)bn * DIM + kt * BK;
#pragma unroll
        for (int it = 0; it < 4; it++) {        // 128 rows x 8 chunks = 1024 / 256
            int idx = tid + it * 256;
            int r = idx >> 3, c = idx & 7;
            CP_ASYNC16(sa + (uint32_t)(r * LDT + c * 4) * 4u, Ag + (size_t)r * DIM + c * 4);
        }
#pragma unroll
        for (int it = 0; it < 4; it++) {
            int idx = tid + it * 256;
            int r = idx >> 3, c = idx & 7;
            CP_ASYNC16(sb2 + (uint32_t)(r * LDT + c * 4) * 4u, Bg + (size_t)r * DIM + c * 4);
        }
        asm volatile("cp.async.commit_group;" ::: "memory");
    };

    load_stage(0, 0);
    load_stage(1, 1);

    for (int j = 0; j < KTILES; j++) {
        if (j == KTILES - 1) asm volatile("cp.async.wait_group 0;" ::: "memory");
        else                 asm volatile("cp.async.wait_group 1;" ::: "memory");
        __syncthreads();

        if (j + 2 < KTILES) load_stage((j + 2) % NSTAGES, j + 2);

        const float* As = sm + (j % NSTAGES) * STAGEF;
        const float* Bs = As + BM * LDT;

#pragma unroll
        for (int ks = 0; ks < 4; ks++) {
            const int k0 = ks * 8;
            uint32_t a[4][4], b[4][2];
#pragma unroll
            for (int mi = 0; mi < 4; mi++) {
                const int r = warp_m * 64 + mi * 16 + g;
                a[mi][0] = rtf32_u(As[r * LDT + k0 + tg]);
                a[mi][1] = rtf32_u(As[(r + 8) * LDT + k0 + tg]);
                a[mi][2] = rtf32_u(As[r * LDT + k0 + tg + 4]);
                a[mi][3] = rtf32_u(As[(r + 8) * LDT + k0 + tg + 4]);
            }
#pragma unroll
            for (int ni = 0; ni < 4; ni++) {
                const int n = warp_n * 32 + ni * 8 + g;
                b[ni][0] = rtf32_u(Bs[n * LDT + k0 + tg]);
                b[ni][1] = rtf32_u(Bs[n * LDT + k0 + tg + 4]);
            }
#pragma unroll
            for (int mi = 0; mi < 4; mi++)
#pragma unroll
                for (int ni = 0; ni < 4; ni++)
                    mma_tf32(acc[mi][ni], a[mi], b[ni]);
        }
        __syncthreads();
    }

    // ---- epilogue ----
#pragma unroll
    for (int mi = 0; mi < 4; mi++) {
        const int r0 = bm + warp_m * 64 + mi * 16 + g;
#pragma unroll
        for (int ni = 0; ni < 4; ni++) {
            const int cc = bn + warp_n * 32 + ni * 8 + 2 * tg;
            float2 v0 = make_float2(acc[mi][ni][0], acc[mi][ni][1]);
            float2 v1 = make_float2(acc[mi][ni][2], acc[mi][ni][3]);
            if (add_bias) {
                const float b0 = bias[cc], b1 = bias[cc + 1];
                v0.x += b0; v0.y += b1;
                v1.x += b0; v1.y += b1;
            }
            *reinterpret_cast<float2*>(&C[(size_t)r0 * DIM + cc]) = v0;
            *reinterpret_cast<float2*>(&C[(size_t)(r0 + 8) * DIM + cc]) = v1;
        }
    }
}

// -------------------- chunked diagonal scan (in place on g_u) --------------
__global__ void __launch_bounds__(256)
scan_carry(const float* __restrict__ Avec)
{
    const int idx = blockIdx.x * blockDim.x + threadIdx.x;  // 131072
    const int n = idx & (DIM - 1);
    const int ch = (idx >> 10) & (CHUNKS - 1);
    const int b = idx >> 14;
    const float a = Avec[n];
    const float* u = g_u + ((size_t)b * SEQ + (size_t)ch * CLEN) * DIM + n;
    float h = 0.0f;
#pragma unroll 4
    for (int t = 0; t < CLEN; t++) h = fmaf(a, h, u[(size_t)t * DIM]);
    g_carry[idx] = h;
}

__global__ void __launch_bounds__(256)
scan_prefix(const float* __restrict__ Avec)
{
    const int idx = blockIdx.x * blockDim.x + threadIdx.x;  // 8192
    const int n = idx & (DIM - 1);
    const int b = idx >> 10;
    const float a = Avec[n];
    float aL = a;
#pragma unroll
    for (int s = 0; s < 7; s++) aL *= aL;   // a^128
    float P = 0.0f;
#pragma unroll
    for (int ch = 0; ch < CHUNKS; ch++) {
        const int o = (b * CHUNKS + ch) * DIM + n;
        g_prefix[o] = P;
        P = fmaf(aL, P, g_carry[o]);
    }
}

__global__ void __launch_bounds__(256)
scan_apply(const float* __restrict__ Avec)
{
    const int idx = blockIdx.x * blockDim.x + threadIdx.x;  // 131072
    const int n = idx & (DIM - 1);
    const int ch = (idx >> 10) & (CHUNKS - 1);
    const int b = idx >> 14;
    const float a = Avec[n];
    float* u = g_u + ((size_t)b * SEQ + (size_t)ch * CLEN) * DIM + n;
    float h = g_prefix[idx];
#pragma unroll 4
    for (int t = 0; t < CLEN; t++) {
        h = fmaf(a, h, u[(size_t)t * DIM]);
        u[(size_t)t * DIM] = h;
    }
}

// -------------------- launch -----------------------------------------------
extern "C" void kernel_launch(void* const* d_in, const int* in_sizes, int n_in,
                              void* d_out, int out_size)
{
    const float* x    = (const float*)d_in[0];
    const float* Avec = (const float*)d_in[1];
    const float* Bmat = (const float*)d_in[2];
    const float* Wmat = (const float*)d_in[3];
    const float* bias = (const float*)d_in[4];
    float* out = (float*)d_out;

    float* u = nullptr;
    cudaGetSymbolAddress((void**)&u, g_u);

    cudaFuncSetAttribute(gemm_tf32mma, cudaFuncAttributeMaxDynamicSharedMemorySize, SMEM_BYTES);

    dim3 grid(DIM / BN, M_TOTAL / BM);  // (8, 128)

    // u = x @ B^T  (tf32 rounding happens in-register inside the GEMM)
    gemm_tf32mma<<<grid, 256, SMEM_BYTES>>>(x, Bmat, nullptr, u, 0);

    // h_t = a h_{t-1} + u_t, chunked, in place
    scan_carry<<<(BATCH * CHUNKS * DIM) / 256, 256>>>(Avec);
    scan_prefix<<<(BATCH * DIM) / 256, 256>>>(Avec);
    scan_apply<<<(BATCH * CHUNKS * DIM) / 256, 256>>>(Avec);

    // y = h @ W^T + b
    gemm_tf32mma<<<grid, 256, SMEM_BYTES>>>(u, Wmat, bias, out, 1);
}